// round 10
// baseline (speedup 1.0000x reference)
#include <cuda_runtime.h>
#include <cuda_bf16.h>

#define BCH   10
#define HH    320
#define WW    1024
#define PTS   500
#define DENSE 2000
#define KMEAN 10
#define NPTS  (BCH * PTS)
#define CHUNKS (DENSE / 4)      // 500 int4 chunks per point

// Window: by in [-7,7] (15 rows), bx in [-11,11] (23 cols), padded to 32 cols.
#define WROWS 15
#define WCOLS 23
#define HSLOTS (WROWS * 32)     // 480

// ONE WARP PER CTA, one point per warp, 170 regs/thread (launch_bounds 32,12).
// The whole 16KB bx/by stream for a point is issued as one front-batched wave
// of ~30 LDG.128 per lane (load-all-then-commit), so a heavy warp pays DRAM
// latency ~once instead of ~5 times. Tail occupancy is heavy-count-limited
// (~8-12 warps/SM), so the lost CTA slots cost nothing where it matters.
__global__ __launch_bounds__(32, 12)
void rsbsp_kernel(const float* __restrict__ disp,
                  const float* __restrict__ fore,
                  const int*   __restrict__ cxs,
                  const int*   __restrict__ cys,
                  const int*   __restrict__ bxs,
                  const int*   __restrict__ bys,
                  float*       __restrict__ out)
{
    __shared__ int hist[HSLOTS];

    const int n    = blockIdx.x;
    const int lane = threadIdx.x;

    const int chan = n / PTS;
    const int cx   = cxs[n];
    const int cy   = cys[n];
    const float* dch = disp + (size_t)chan * (HH * WW);
    const float* fch = fore + (size_t)chan * (HH * WW);
    const int    base = (cy << 10) + cx;          // WW == 1024

    // ---- validity: maxpool3x3(|sobel_x(forepred)|)(cy,cx) > 3.1
    //      && disp(cy,cx) > 0.007.  Centers >= 11 px from all borders.
    float g = 0.0f;
    if (lane < 9) {
        const int dy = lane / 3 - 1;
        const int dx = lane % 3 - 1;
        const float* p = fch + (size_t)(cy + dy - 1) * WW + (cx + dx);
        const float a = p[1]  + 2.0f * p[WW + 1] + p[2 * WW + 1];
        const float b = p[-1] + 2.0f * p[WW - 1] + p[2 * WW - 1];
        g = fabsf(a - b);
    }
    const float dC = dch[base];

    // zero histogram while the validity loads are in flight
    #pragma unroll
    for (int r = 0; r < WROWS; r++) hist[lane + (r << 5)] = 0;

    #pragma unroll
    for (int o = 16; o; o >>= 1) g = fmaxf(g, __shfl_xor_sync(0xFFFFFFFFu, g, o));
    if (!((g > 3.1f) && (dC > 0.007f))) {
        if (lane == 0) { out[2 * n] = 0.0f; out[2 * n + 1] = 0.0f; }
        return;                                   // CTA slot freed immediately
    }
    __syncwarp();

    // ---- histogram of the 2000 samples: LOAD-ALL then COMMIT-ALL ----------
    // 16 groups x 2 int4 = 128 data regs; launch_bounds gives 170 regs so
    // ptxas can keep ~all loads in flight (MLP ~30 per lane).
    const int4* bx4p = (const int4*)(bxs + (size_t)n * DENSE);
    const int4* by4p = (const int4*)(bys + (size_t)n * DENSE);

    int4 B[16], Y[16];
    #pragma unroll
    for (int k = 0; k < 16; k++) {
        const int  c     = lane + (k << 5);
        const bool valid = (k < 15) || (c < CHUNKS);   // compile-time true k<15
        if (valid) {
            B[k] = bx4p[c];
            Y[k] = by4p[c];
        } else {
            B[k] = make_int4(-11, -11, -11, -11);      // alias to slot 0 row 0
            Y[k] = make_int4(-7, -7, -7, -7);          // harmless: counted then
        }                                              // subtracted? NO - guard below
    }
    #pragma unroll
    for (int k = 0; k < 16; k++) {
        const int  c     = lane + (k << 5);
        const bool valid = (k < 15) || (c < CHUNKS);
        if (valid) {
            // slot = (y+7)*32 + (x+11) = y*32 + x + 235
            atomicAdd(&hist[(Y[k].x << 5) + B[k].x + 235], 1);
            atomicAdd(&hist[(Y[k].y << 5) + B[k].y + 235], 1);
            atomicAdd(&hist[(Y[k].z << 5) + B[k].z + 235], 1);
            atomicAdd(&hist[(Y[k].w << 5) + B[k].w + 235], 1);
        }
    }
    __syncwarp();

    // ---- weighted stats over the 15x23 window -----------------------------
    float val [WROWS];
    float prod[WROWS];
    float cntf[WROWS];
    float mx = -1e30f, mn = 1e30f, stot = 0.0f;
    #pragma unroll
    for (int r = 0; r < WROWS; r++) {
        const int   cnt = hist[lane + (r << 5)];
        const float v   = (lane < WCOLS)
                        ? dch[base + (r - 7) * WW + (lane - 11)]   // coalesced row
                        : 0.0f;
        const float cf  = (float)cnt;
        val[r]  = v;
        cntf[r] = cf;
        prod[r] = v * cf;
        stot   += prod[r];
        if (cnt > 0) { mx = fmaxf(mx, v); mn = fminf(mn, v); }
    }
    #pragma unroll
    for (int o = 16; o; o >>= 1) {
        mx   = fmaxf(mx, __shfl_xor_sync(0xFFFFFFFFu, mx, o));
        mn   = fminf(mn, __shfl_xor_sync(0xFFFFFFFFu, mn, o));
        stot +=          __shfl_xor_sync(0xFFFFFFFFu, stot, o);
    }

    // ---- weighted 2-cluster 1-D k-means over <=345 unique values ----------
    // kL > kS => |s-kL|<=|s-kS| <=> s >= (kL+kS)/2 (midpoint tie -> large,
    // matching dl<=ds). Threshold acts on val only, so weighted sums equal the
    // per-sample sums exactly (same partition). Bitwise fixed point => the
    // remaining reference iterations are no-ops -> exact early exit.
    float kL = mx, kS = mn;
    float lastCnt = 0.0f;
    #pragma unroll 1
    for (int it = 0; it < KMEAN; it++) {
        const float mid = 0.5f * (kL + kS);
        float sumL = 0.0f, cntL = 0.0f;
        #pragma unroll
        for (int r = 0; r < WROWS; r++) {
            if (val[r] >= mid) { sumL += prod[r]; cntL += cntf[r]; }
        }
        #pragma unroll
        for (int o = 16; o; o >>= 1) {
            sumL += __shfl_xor_sync(0xFFFFFFFFu, sumL, o);
            cntL += __shfl_xor_sync(0xFFFFFFFFu, cntL, o);
        }
        const float nkL = __fdividef(sumL, cntL);
        const float nkS = __fdividef(stot - sumL, (float)DENSE - cntL);
        lastCnt = cntL;
        const bool conv = (nkL == kL) && (nkS == kS);
        kL = nkL; kS = nkS;
        if (conv) break;
    }

    const bool keep = ((kL - kS) > 0.005f) && (lastCnt > 5.0f);
    if (lane == 0) {
        const float kf = keep ? 1.0f : 0.0f;
        out[2 * n]     = kL * kf;
        out[2 * n + 1] = kS * kf;
    }
}

extern "C" void kernel_launch(void* const* d_in, const int* in_sizes, int n_in,
                              void* d_out, int out_size)
{
    const float* disp = (const float*)d_in[0];
    const float* fore = (const float*)d_in[1];
    const int*   cxs  = (const int*)  d_in[2];
    const int*   cys  = (const int*)  d_in[3];
    const int*   bxs  = (const int*)  d_in[4];
    const int*   bys  = (const int*)  d_in[5];
    float*       out  = (float*)d_out;

    rsbsp_kernel<<<NPTS, 32>>>(disp, fore, cxs, cys, bxs, bys, out);
}

// round 11
// speedup vs baseline: 1.1522x; 1.1522x over previous
#include <cuda_runtime.h>
#include <cuda_bf16.h>
#include <cstdint>

#define BCH   10
#define HH    320
#define WW    1024
#define PTS   500
#define DENSE 2000
#define KMEAN 10
#define NPTS  (BCH * PTS)
#define CHUNKS (DENSE / 4)      // 500 int4 chunks per point

// Window: by in [-7,7] (15 rows), bx in [-11,11] (23 cols), padded to 32 cols.
#define WROWS 15
#define WCOLS 23
#define HSLOTS (WROWS * 32)     // 480

#define ROW_BYTES (DENSE * 4)   // 8000 B per bx/by row (16B-aligned: n*8000)

__device__ __forceinline__ uint32_t smem_u32(const void* p) {
    return (uint32_t)__cvta_generic_to_shared(p);
}

// ONE WARP PER CTA, one point per warp. The 16KB bx/by stream per heavy point
// is fetched by TWO cp.async.bulk ops (zero registers, full 16KB in flight),
// landed in smem, then committed to the histogram via conflict-free LDS.128
// + spread ATOMS. MLP is no longer register-limited.
__global__ __launch_bounds__(32)
void rsbsp_kernel(const float* __restrict__ disp,
                  const float* __restrict__ fore,
                  const int*   __restrict__ cxs,
                  const int*   __restrict__ cys,
                  const int*   __restrict__ bxs,
                  const int*   __restrict__ bys,
                  float*       __restrict__ out)
{
    __shared__ alignas(16) int s_bx[DENSE];
    __shared__ alignas(16) int s_by[DENSE];
    __shared__ int hist[HSLOTS];
    __shared__ alignas(8) unsigned long long s_mbar;

    const int n    = blockIdx.x;
    const int lane = threadIdx.x;

    const uint32_t mbar = smem_u32(&s_mbar);
    if (lane == 0) {
        asm volatile("mbarrier.init.shared.b64 [%0], %1;" :: "r"(mbar), "r"(1) : "memory");
    }
    // shfl reductions below warp-synchronize, guaranteeing init ordering.

    const int chan = n / PTS;
    const int cx   = cxs[n];
    const int cy   = cys[n];
    const float* dch = disp + (size_t)chan * (HH * WW);
    const float* fch = fore + (size_t)chan * (HH * WW);
    const int    base = (cy << 10) + cx;          // WW == 1024

    // ---- validity: maxpool3x3(|sobel_x(forepred)|)(cy,cx) > 3.1
    //      && disp(cy,cx) > 0.007.  Centers >= 11 px from all borders.
    float g = 0.0f;
    if (lane < 9) {
        const int dy = lane / 3 - 1;
        const int dx = lane % 3 - 1;
        const float* p = fch + (size_t)(cy + dy - 1) * WW + (cx + dx);
        const float a = p[1]  + 2.0f * p[WW + 1] + p[2 * WW + 1];
        const float b = p[-1] + 2.0f * p[WW - 1] + p[2 * WW - 1];
        g = fabsf(a - b);
    }
    const float dC = dch[base];

    #pragma unroll
    for (int o = 16; o; o >>= 1) g = fmaxf(g, __shfl_xor_sync(0xFFFFFFFFu, g, o));
    if (!((g > 3.1f) && (dC > 0.007f))) {
        if (lane == 0) { out[2 * n] = 0.0f; out[2 * n + 1] = 0.0f; }
        return;                                   // CTA slot freed immediately
    }

    // ---- bulk-copy the full bx/by rows into smem (16KB in flight, 0 regs) --
    if (lane == 0) {
        asm volatile("mbarrier.arrive.expect_tx.shared.b64 _, [%0], %1;"
                     :: "r"(mbar), "r"(2 * ROW_BYTES) : "memory");
        asm volatile("cp.async.bulk.shared::cta.global.mbarrier::complete_tx::bytes "
                     "[%0], [%1], %2, [%3];"
                     :: "r"(smem_u32(s_bx)), "l"(bxs + (size_t)n * DENSE),
                        "r"(ROW_BYTES), "r"(mbar) : "memory");
        asm volatile("cp.async.bulk.shared::cta.global.mbarrier::complete_tx::bytes "
                     "[%0], [%1], %2, [%3];"
                     :: "r"(smem_u32(s_by)), "l"(bys + (size_t)n * DENSE),
                        "r"(ROW_BYTES), "r"(mbar) : "memory");
    }

    // zero histogram while the bulk copies fly
    #pragma unroll
    for (int r = 0; r < WROWS; r++) hist[lane + (r << 5)] = 0;

    // wait for both copies (phase 0), acquire ordering for the smem reads
    {
        uint32_t done;
        asm volatile(
            "{\n\t.reg .pred p;\n\t"
            "mbarrier.try_wait.parity.acquire.cta.shared::cta.b64 p, [%1], 0;\n\t"
            "selp.b32 %0, 1, 0, p;\n\t}"
            : "=r"(done) : "r"(mbar) : "memory");
        if (!done) {
            asm volatile(
                "{\n\t.reg .pred P1;\n\t"
                "WL_%=:\n\t"
                "mbarrier.try_wait.parity.acquire.cta.shared::cta.b64 P1, [%0], 0, 0x989680;\n\t"
                "@P1 bra.uni WD_%=;\n\t"
                "bra.uni WL_%=;\n\t"
                "WD_%=:\n\t}"
                :: "r"(mbar) : "memory");
        }
    }
    __syncwarp();

    // ---- histogram commit from smem (conflict-free LDS.128 + spread ATOMS) -
    const int4* sbx4 = (const int4*)s_bx;
    const int4* sby4 = (const int4*)s_by;
    #pragma unroll 8
    for (int k = 0; k < 16; k++) {
        const int  c     = lane + (k << 5);
        const bool valid = (k < 15) || (c < CHUNKS);   // compile-time true k<15
        if (valid) {
            const int4 b4 = sbx4[c];
            const int4 y4 = sby4[c];
            // slot = (y+7)*32 + (x+11) = y*32 + x + 235
            atomicAdd(&hist[(y4.x << 5) + b4.x + 235], 1);
            atomicAdd(&hist[(y4.y << 5) + b4.y + 235], 1);
            atomicAdd(&hist[(y4.z << 5) + b4.z + 235], 1);
            atomicAdd(&hist[(y4.w << 5) + b4.w + 235], 1);
        }
    }
    __syncwarp();

    // ---- weighted stats over the 15x23 window -----------------------------
    float val [WROWS];
    float prod[WROWS];
    float cntf[WROWS];
    float mx = -1e30f, mn = 1e30f, stot = 0.0f;
    #pragma unroll
    for (int r = 0; r < WROWS; r++) {
        const int   cnt = hist[lane + (r << 5)];
        const float v   = (lane < WCOLS)
                        ? dch[base + (r - 7) * WW + (lane - 11)]   // coalesced row
                        : 0.0f;
        const float cf  = (float)cnt;
        val[r]  = v;
        cntf[r] = cf;
        prod[r] = v * cf;
        stot   += prod[r];
        if (cnt > 0) { mx = fmaxf(mx, v); mn = fminf(mn, v); }
    }
    #pragma unroll
    for (int o = 16; o; o >>= 1) {
        mx   = fmaxf(mx, __shfl_xor_sync(0xFFFFFFFFu, mx, o));
        mn   = fminf(mn, __shfl_xor_sync(0xFFFFFFFFu, mn, o));
        stot +=          __shfl_xor_sync(0xFFFFFFFFu, stot, o);
    }

    // ---- weighted 2-cluster 1-D k-means over <=345 unique values ----------
    // kL > kS => |s-kL|<=|s-kS| <=> s >= (kL+kS)/2 (midpoint tie -> large,
    // matching dl<=ds). Threshold acts on val only, so weighted sums equal the
    // per-sample sums exactly (same partition). Bitwise fixed point => the
    // remaining reference iterations are no-ops -> exact early exit.
    float kL = mx, kS = mn;
    float lastCnt = 0.0f;
    #pragma unroll 1
    for (int it = 0; it < KMEAN; it++) {
        const float mid = 0.5f * (kL + kS);
        float sumL = 0.0f, cntL = 0.0f;
        #pragma unroll
        for (int r = 0; r < WROWS; r++) {
            if (val[r] >= mid) { sumL += prod[r]; cntL += cntf[r]; }
        }
        #pragma unroll
        for (int o = 16; o; o >>= 1) {
            sumL += __shfl_xor_sync(0xFFFFFFFFu, sumL, o);
            cntL += __shfl_xor_sync(0xFFFFFFFFu, cntL, o);
        }
        const float nkL = __fdividef(sumL, cntL);
        const float nkS = __fdividef(stot - sumL, (float)DENSE - cntL);
        lastCnt = cntL;
        const bool conv = (nkL == kL) && (nkS == kS);
        kL = nkL; kS = nkS;
        if (conv) break;
    }

    const bool keep = ((kL - kS) > 0.005f) && (lastCnt > 5.0f);
    if (lane == 0) {
        const float kf = keep ? 1.0f : 0.0f;
        out[2 * n]     = kL * kf;
        out[2 * n + 1] = kS * kf;
    }
}

extern "C" void kernel_launch(void* const* d_in, const int* in_sizes, int n_in,
                              void* d_out, int out_size)
{
    const float* disp = (const float*)d_in[0];
    const float* fore = (const float*)d_in[1];
    const int*   cxs  = (const int*)  d_in[2];
    const int*   cys  = (const int*)  d_in[3];
    const int*   bxs  = (const int*)  d_in[4];
    const int*   bys  = (const int*)  d_in[5];
    float*       out  = (float*)d_out;

    rsbsp_kernel<<<NPTS, 32>>>(disp, fore, cxs, cys, bxs, bys, out);
}